// round 7
// baseline (speedup 1.0000x reference)
#include <cuda_runtime.h>
#include <cuda_fp16.h>

// int4-quantized GEMV, QB=128, K=8192. fp16 tensors arrive upcast to fp32.
//   d_in[0] x       : float[8192]
//   d_in[1] packed_w: int32[N, 4096]  (low/high nibble per int32, offset-8)
//   d_in[2] scales  : float[N, 64]
//   d_out  out      : float[N]
//
// R5: persistent CTAs (148*4) + per-warp row stealing via global atomic
// counter (reset by a tiny init launch each call -> deterministic &
// graph-capturable). Kills SM block-count imbalance (68 SMs had 4 CTAs vs 80
// with 3 -> ~25% tail at low BW). x staged once per CTA as half2 (lossless,
// conflict-free LDS.128); nibble->fp16 0x6400 trick; fp32 accumulation;
// scales in registers + single SHFL.IDX per iteration; __ldcs streaming.

#define FAST_K 8192
#define PERSIST_CTAS (148 * 4)

__device__ unsigned g_work;

__global__ void reset_work() { g_work = 0u; }

__global__ void __launch_bounds__(256, 4)
q4gemv_persist(const float* __restrict__ x,
               const int*   __restrict__ pw,
               const float* __restrict__ scales,
               float*       __restrict__ out,
               int N)
{
    __shared__ __half xs[FAST_K];                 // 16 KB

    const int tid = threadIdx.x;

    // Stage x once per CTA: fp32 -> fp16 (lossless; data originated fp16).
    {
        const float4* xsrc = reinterpret_cast<const float4*>(x);
        uint2*        xdst = reinterpret_cast<uint2*>(xs);
        #pragma unroll
        for (int i = 0; i < 8; ++i) {             // 2048 float4 / 256 thr
            const int idx = tid + i * 256;
            float4 v = xsrc[idx];
            __half2 a = __floats2half2_rn(v.x, v.y);
            __half2 b = __floats2half2_rn(v.z, v.w);
            uint2 u;
            u.x = *reinterpret_cast<unsigned*>(&a);
            u.y = *reinterpret_cast<unsigned*>(&b);
            xdst[idx] = u;
        }
    }
    __syncthreads();

    const int lane = tid & 31;
    const uint4* xsv = reinterpret_cast<const uint4*>(xs);

    const unsigned off_bits = 0x64086408u;        // half2(1032, 1032)
    const __half2 off = *reinterpret_cast<const __half2*>(&off_bits);

    // First steal.
    unsigned row = 0u;
    if (lane == 0) row = atomicAdd(&g_work, 1u);
    row = __shfl_sync(0xffffffffu, row, 0);

    while (row < (unsigned)N) {
        // Prefetch next row id; its latency hides behind this row's work.
        unsigned nrow = 0u;
        if (lane == 0) nrow = atomicAdd(&g_work, 1u);
        nrow = __shfl_sync(0xffffffffu, nrow, 0);

        const uint4* prow = reinterpret_cast<const uint4*>(pw)
                          + (size_t)row * (FAST_K / 8);
        // Row scales in registers: lane l holds blocks l and 32+l.
        const float s0 = scales[(size_t)row * 64 + lane];
        const float s1 = scales[(size_t)row * 64 + 32 + lane];

        float acc = 0.0f;

        #pragma unroll 4
        for (int it = 0; it < 32; ++it) {
            const int c = it * 32 + lane;         // 8-weight chunk 0..1023
            uint4 w  = __ldcs(prow + c);          // streaming weights
            uint4 xv = xsv[c];

            // Quant block = 2*it + (lane>=16); fetch from lane 2*(it&15)+(lane>>4).
            const float ssrc = (it < 16) ? s0 : s1;
            const float s = __shfl_sync(0xffffffffu, ssrc,
                                        2 * (it & 15) + (lane >> 4));

            float p = 0.0f;
            #pragma unroll
            for (int j = 0; j < 4; ++j) {
                const unsigned b = reinterpret_cast<const unsigned*>(&w)[j];
                // half2(1024+lo, 1024+hi), exact subtract 1032 -> (lo-8, hi-8)
                unsigned t = ((b | (b << 12)) & 0x000F000Fu) | 0x64006400u;
                __half2 w2 = __hsub2(*reinterpret_cast<const __half2*>(&t), off);
                float2 wf = __half22float2(w2);
                float2 xf = __half22float2(
                    reinterpret_cast<const __half2*>(&xv)[j]);
                p = fmaf(wf.x, xf.x, p);
                p = fmaf(wf.y, xf.y, p);
            }
            acc = fmaf(p, s, acc);
        }

        #pragma unroll
        for (int o = 16; o; o >>= 1)
            acc += __shfl_xor_sync(0xffffffffu, acc, o);

        if (lane == 0)
            out[row] = acc;

        row = nrow;
    }
}

// Generic fallback (any K / QB / N), fp32 in/out.
__global__ void q4gemv_generic(const float* __restrict__ x,
                               const int*   __restrict__ pw,
                               const float* __restrict__ scales,
                               float*       __restrict__ out,
                               int N, int K, int QB)
{
    int row = blockIdx.x * blockDim.x + threadIdx.x;
    if (row >= N) return;
    const int halfK = K / 2;
    const int nblk  = K / QB;
    const int ipb   = QB / 2;
    float acc = 0.0f;
    for (int blk = 0; blk < nblk; ++blk) {
        float p = 0.0f;
        for (int i = 0; i < ipb; ++i) {
            int idx = blk * ipb + i;
            unsigned b = (unsigned)pw[(size_t)row * halfK + idx];
            float lo = (float)(int)(b & 15u) - 8.0f;
            float hi = (float)(int)((b >> 4) & 15u) - 8.0f;
            p = fmaf(lo, x[2 * idx],     p);
            p = fmaf(hi, x[2 * idx + 1], p);
        }
        acc = fmaf(p, scales[(size_t)row * nblk + blk], acc);
    }
    out[row] = acc;
}

extern "C" void kernel_launch(void* const* d_in, const int* in_sizes, int n_in,
                              void* d_out, int out_size)
{
    const float* x  = (const float*)d_in[0];
    const int*   pw = (const int*)  d_in[1];
    const float* sc = (const float*)d_in[2];
    float*       out = (float*)d_out;

    const long long K_ll = in_sizes[0];
    const int K  = (int)K_ll;
    const int N  = (int)(((long long)in_sizes[1] * 2) / K_ll);
    const int QB = (int)(((long long)N * K_ll) / in_sizes[2]);

    if (K == FAST_K && QB == 128) {
        reset_work<<<1, 1>>>();
        q4gemv_persist<<<PERSIST_CTAS, 256>>>(x, pw, sc, out, N);
    } else {
        int threads = 256;
        int blocks = (N + threads - 1) / threads;
        q4gemv_generic<<<blocks, threads>>>(x, pw, sc, out, N, K, QB);
    }
}